// round 15
// baseline (speedup 1.0000x reference)
#include <cuda_runtime.h>
#include <cstdint>

// AdditiveModel on GB300 — R14: R13 tensor-core kernel at 3 CTAs/SM.
// Warp batch tile 64 -> 32 rows (T=2): x smem halves -> 72.7KB -> rounds to
// 72KB -> 3 CTAs (24 warps/SM). In R13 nothing was above 44% utilization and
// issue was 18.4% — purely latency-bound at 4 warps/SMSP, so +50% warps should
// convert almost directly to issue throughput (instr/batch tax only ~+19%).
//
//   sigmoid(z) = 0.5*tanh(0.5 z) + 0.5
//   conv1: C1 = x @ (0.5*mask*W1_perm)^T + 0.5 b1_perm ; t1 = tanh(C1)
//   conv2: C2 = t1 @ (0.25*W2)^T + (0.25*rowsum(W2)+0.5 b2) ; t2 = tanh(C2)
//   out   = sum 0.5*w3*t2 + (b3 + 0.5*sum w3)
// h-permutation pi(q) = (q>>1)+(q&1)*4 per 8-block makes conv1 C-frag layout
// = conv2 A-frag layout (register renaming, no shuffles). x fed as raw float
// bits (tf32 truncation, validated R12/R13).

#define NV 16
#define BB 32768

__device__ __forceinline__ float tanh_fast(float x) {
    float t; asm("tanh.approx.f32 %0, %1;" : "=f"(t) : "f"(x)); return t;
}
__device__ __forceinline__ uint32_t f2tf32(float x) {
    uint32_t r; asm("cvt.rna.tf32.f32 %0, %1;" : "=r"(r) : "f"(x)); return r;
}
__device__ __forceinline__ void mma_tf32(float* d,
                                         uint32_t a0, uint32_t a1, uint32_t a2, uint32_t a3,
                                         uint32_t b0, uint32_t b1) {
    asm("mma.sync.aligned.m16n8k8.row.col.f32.tf32.tf32.f32 "
        "{%0,%1,%2,%3}, {%4,%5,%6,%7}, {%8,%9}, {%0,%1,%2,%3};"
        : "+f"(d[0]), "+f"(d[1]), "+f"(d[2]), "+f"(d[3])
        : "r"(a0), "r"(a1), "r"(a2), "r"(a3), "r"(b0), "r"(b1));
}
__device__ __forceinline__ int permh(int q) {
    return (q & 8) | ((q & 7) >> 1) | ((q & 1) << 2);
}

// dynamic smem (floats):
//   sX [8 warps][2 slots][32 rows][18]   36864 B  (pitch-18 rows)
//   sW1 [16 j][16 l][16 hcol] tf32       16384 B  (0.5*mask folded, cols pi-permuted)
//   sW2t[16 j][16 h][16 k]   tf32        16384 B  (0.25 folded)
//   sB1(perm)/sB2/sW3 [16 j][16]          3072 B
//   sOutC                                   16 B   total 72720 -> 72KB -> 3 CTAs
#define SMEM_BYTES (36864 + 16384 + 16384 + 1024 + 1024 + 1024 + 16)

__global__ __launch_bounds__(256, 3)
void additive_model_kernel(const float* __restrict__ x,
                           const int*   __restrict__ causal,
                           const float* __restrict__ W1,
                           const float* __restrict__ b1,
                           const float* __restrict__ W2,
                           const float* __restrict__ b2,
                           const float* __restrict__ W3,
                           const float* __restrict__ b3,
                           float* __restrict__ out)
{
    extern __shared__ float smem[];
    float*    sX    = smem;                      // 9216 floats
    uint32_t* sW1u  = (uint32_t*)(smem + 9216);  // 4096
    uint32_t* sW2u  = sW1u + 4096;               // 4096
    float*    sB1   = (float*)(sW2u + 4096);     // 256
    float*    sB2   = sB1 + 256;
    float*    sW3   = sB2 + 256;
    float*    sOutC = sW3 + 256;

    const int v    = blockIdx.x & 15;
    const int bblk = blockIdx.x >> 4;
    const int tid  = threadIdx.x;
    const int wid  = tid >> 5;
    const int lane = tid & 31;
    const int r    = lane >> 2;   // 0..7
    const int c    = lane & 3;    // 0..3
    const int g0   = v * 16;

    // ---- stage weights (tf32-rounded, scales/mask folded, W1 cols permuted) ----
    #pragma unroll
    for (int i = 0; i < 16; ++i) {
        const int e = tid + i * 256;           // 0..4095
        const int j = e >> 8;
        const int a = (e >> 4) & 15;           // l for W1, h for W2t
        const int b = e & 15;                  // hcol for W1, k for W2t
        const int g = g0 + j;
        const float ms = (causal[g * 16 + a] != 0) ? 0.5f : 0.0f;
        sW1u[e] = f2tf32(ms * W1[(g * 16 + permh(b)) * 16 + a]);
        sW2u[e] = f2tf32(0.25f * W2[g * 256 + b * 16 + a]);
    }
    {   // biases + w3; b1 permuted like W1 cols
        const int j = tid >> 4, q = tid & 15;
        const int g = g0 + j;
        sB1[tid] = 0.5f * b1[g * 16 + permh(q)];
        float s0 = 0.f;
        #pragma unroll
        for (int h = 0; h < 16; ++h) s0 += W2[g * 256 + q * 16 + h];
        sB2[tid] = 0.25f * s0 + 0.5f * b2[g * 16 + q];
        sW3[tid] = 0.5f * W3[v * 256 + j * 16 + q];
    }
    if (tid == 0) {
        float cc = b3[v];
        #pragma unroll 1
        for (int m = 0; m < 256; ++m) cc += 0.5f * W3[v * 256 + m];
        *sOutC = cc;
    }
    __syncthreads();   // only CTA barrier

    // ---- warp-private x staging: 32 rows x 16 floats per j, pitch 18 ----
    const float* xw = x + (size_t)(bblk * 256 + wid * 32) * 4096 + g0 * 16;
    float* slotB = sX + wid * 1152;        // 2 slots * 576 floats

    const int srow = lane >> 3;            // 0..3
    const int su   = lane & 7;             // 0..7
    const uint32_t dstage = (uint32_t)__cvta_generic_to_shared(
                                slotB + srow * 18 + su * 2);
    const float* sstage = xw + (size_t)srow * 4096 + su * 2;

    #define STAGE_J(j_)                                                               \
        do {                                                                          \
            const uint32_t _d = dstage + ((j_) & 1) * 2304;  /* slot = 576 fl */      \
            const float*   _s = sstage + (j_) * 16;                                   \
            _Pragma("unroll")                                                         \
            for (int _i = 0; _i < 8; ++_i) {                                          \
                asm volatile("cp.async.ca.shared.global [%0], [%1], 8;"               \
                             :: "r"(_d + _i * 288),          /* 4 rows = 72 fl */     \
                                "l"(_s + (size_t)_i * 16384) /* 4 rows of x   */ );   \
            }                                                                         \
            asm volatile("cp.async.commit_group;");                                   \
        } while (0)

    STAGE_J(0);
    STAGE_J(1);

    float sp[4];   // [T][rowhalf] accumulators across j
    #pragma unroll
    for (int i = 0; i < 4; ++i) sp[i] = 0.0f;

    #pragma unroll 1
    for (int j = 0; j < 16; ++j) {
        if (j < 15) { asm volatile("cp.async.wait_group 1;" ::: "memory"); }
        else        { asm volatile("cp.async.wait_group 0;" ::: "memory"); }
        __syncwarp();

        const uint32_t* xs = (const uint32_t*)(slotB + (j & 1) * 576);

        // ---- x A-fragments: raw float bits as tf32 (truncation) ----
        uint32_t xa[2][8];
        #pragma unroll
        for (int T = 0; T < 2; ++T) {
            #pragma unroll
            for (int kh = 0; kh < 2; ++kh) {
                const int base = (T * 16 + r) * 18 + kh * 8 + c;
                xa[T][kh * 4 + 0] = xs[base];
                xa[T][kh * 4 + 1] = xs[base + 8 * 18];
                xa[T][kh * 4 + 2] = xs[base + 4];
                xa[T][kh * 4 + 3] = xs[base + 8 * 18 + 4];
            }
        }

        if (j < 14) STAGE_J(j + 2);   // slot free after x loads

        // ---- weight B-fragments (warp-wide, reused across tiles) ----
        uint32_t w1b[2][2][2], w2b[2][2][2];
        #pragma unroll
        for (int kh = 0; kh < 2; ++kh)
            #pragma unroll
            for (int nh = 0; nh < 2; ++nh) {
                const int o = j * 256 + (kh * 8 + c) * 16 + nh * 8 + r;
                w1b[kh][nh][0] = sW1u[o];
                w1b[kh][nh][1] = sW1u[o + 4 * 16];
                w2b[kh][nh][0] = sW2u[o];
                w2b[kh][nh][1] = sW2u[o + 4 * 16];
            }
        float b1v[2][2], b2v[2][2], w3v[2][2];
        #pragma unroll
        for (int nh = 0; nh < 2; ++nh) {
            b1v[nh][0] = sB1[j * 16 + nh * 8 + 2 * c];
            b1v[nh][1] = sB1[j * 16 + nh * 8 + 2 * c + 1];
            b2v[nh][0] = sB2[j * 16 + nh * 8 + 2 * c];
            b2v[nh][1] = sB2[j * 16 + nh * 8 + 2 * c + 1];
            w3v[nh][0] = sW3[j * 16 + nh * 8 + 2 * c];
            w3v[nh][1] = sW3[j * 16 + nh * 8 + 2 * c + 1];
        }

        // ---- per 16-batch tile: conv1 mma -> tanh (renamed A) -> conv2 mma -> epi ----
        #pragma unroll
        for (int T = 0; T < 2; ++T) {
            float C1[2][4];
            #pragma unroll
            for (int nh = 0; nh < 2; ++nh) {
                C1[nh][0] = b1v[nh][0]; C1[nh][1] = b1v[nh][1];
                C1[nh][2] = b1v[nh][0]; C1[nh][3] = b1v[nh][1];
                mma_tf32(C1[nh], xa[T][0], xa[T][1], xa[T][2], xa[T][3],
                         w1b[0][nh][0], w1b[0][nh][1]);
                mma_tf32(C1[nh], xa[T][4], xa[T][5], xa[T][6], xa[T][7],
                         w1b[1][nh][0], w1b[1][nh][1]);
            }

            // tanh in place; C-layout IS conv2 A-layout after pi-permutation
            uint32_t a2f[2][4];
            #pragma unroll
            for (int kh = 0; kh < 2; ++kh) {
                a2f[kh][0] = __float_as_uint(tanh_fast(C1[kh][0]));
                a2f[kh][1] = __float_as_uint(tanh_fast(C1[kh][2]));
                a2f[kh][2] = __float_as_uint(tanh_fast(C1[kh][1]));
                a2f[kh][3] = __float_as_uint(tanh_fast(C1[kh][3]));
            }

            float C2[2][4];
            #pragma unroll
            for (int nh = 0; nh < 2; ++nh) {
                C2[nh][0] = b2v[nh][0]; C2[nh][1] = b2v[nh][1];
                C2[nh][2] = b2v[nh][0]; C2[nh][3] = b2v[nh][1];
                mma_tf32(C2[nh], a2f[0][0], a2f[0][1], a2f[0][2], a2f[0][3],
                         w2b[0][nh][0], w2b[0][nh][1]);
                mma_tf32(C2[nh], a2f[1][0], a2f[1][1], a2f[1][2], a2f[1][3],
                         w2b[1][nh][0], w2b[1][nh][1]);
            }

            // epilogue: sp[T][rowhalf] += 0.5*w3[k] * tanh(C2)
            #pragma unroll
            for (int nh = 0; nh < 2; ++nh) {
                sp[T * 2 + 0] = fmaf(tanh_fast(C2[nh][0]), w3v[nh][0], sp[T * 2 + 0]);
                sp[T * 2 + 0] = fmaf(tanh_fast(C2[nh][1]), w3v[nh][1], sp[T * 2 + 0]);
                sp[T * 2 + 1] = fmaf(tanh_fast(C2[nh][2]), w3v[nh][0], sp[T * 2 + 1]);
                sp[T * 2 + 1] = fmaf(tanh_fast(C2[nh][3]), w3v[nh][1], sp[T * 2 + 1]);
            }
        }
    }
    #undef STAGE_J

    // ---- quad-reduce over c lanes and write out ----
    const float outC = *sOutC;
    #pragma unroll
    for (int T = 0; T < 2; ++T)
        #pragma unroll
        for (int s = 0; s < 2; ++s) {
            float vs = sp[T * 2 + s];
            vs += __shfl_xor_sync(0xffffffffu, vs, 1, 4);
            vs += __shfl_xor_sync(0xffffffffu, vs, 2, 4);
            if (c == 0) {
                const int b = bblk * 256 + wid * 32 + T * 16 + r + 8 * s;
                out[(size_t)b * NV + v] = vs + outC;
            }
        }
}

extern "C" void kernel_launch(void* const* d_in, const int* in_sizes, int n_in,
                              void* d_out, int out_size)
{
    const float* x      = (const float*)d_in[0];
    const int*   causal = (const int*)  d_in[1];
    const float* W1     = (const float*)d_in[2];
    const float* b1     = (const float*)d_in[3];
    const float* W2     = (const float*)d_in[4];
    const float* b2     = (const float*)d_in[5];
    const float* W3     = (const float*)d_in[6];
    const float* b3     = (const float*)d_in[7];
    float* out = (float*)d_out;

    static int configured = 0;
    if (!configured) {
        cudaFuncSetAttribute(additive_model_kernel,
                             cudaFuncAttributeMaxDynamicSharedMemorySize, SMEM_BYTES);
        configured = 1;
    }

    dim3 grid((BB / 256) * NV);   // 128 batch blocks * 16 variables = 2048 CTAs
    additive_model_kernel<<<grid, 256, SMEM_BYTES>>>(x, causal, W1, b1, W2, b2, W3, b3, out);
}